// round 6
// baseline (speedup 1.0000x reference)
#include <cuda_runtime.h>
#include <cuda_bf16.h>

#define NCLUST 256
#define NPT    128
#define NEDGE  1024
#define VS     32
#define VOXN   (VS*VS*VS)   // 32768

typedef unsigned long long ull;

// packed fp32x2 helpers (FFMA2 — only reachable via PTX)
__device__ __forceinline__ ull pk2(float lo, float hi) {
    ull r; asm("mov.b64 %0, {%1,%2};" : "=l"(r) : "f"(lo), "f"(hi)); return r;
}
__device__ __forceinline__ void fma2(ull& d, ull a, ull b) {
    asm("fma.rn.f32x2 %0, %1, %2, %0;" : "+l"(d) : "l"(a), "l"(b));
}
__device__ __forceinline__ float2 upk2(ull v) {
    float2 r; asm("mov.b64 {%0,%1}, %2;" : "=f"(r.x), "=f"(r.y) : "l"(v)); return r;
}

// Scratch (device globals)
__device__ float g_cvox[NCLUST * VOXN];              // 32 MB
__device__ float g_c1c[NCLUST * 16 * 4096];          // 67 MB per-CLUSTER linear conv1
__device__ float g_c2[NEDGE * 32 * 8 * 8 * 8];       // 67 MB
__device__ int   g_eidx_is_i64;
__device__ int   g_mask_is_u8;

// ---------------------------------------------------------------------------
// Kernel D: dtype layout detection
// ---------------------------------------------------------------------------
__global__ void detect_kernel(const int* __restrict__ eidx_w,
                              const unsigned int* __restrict__ mask_w,
                              int E, int maskWords)
{
    __shared__ int oddNZ, bigW;
    if (threadIdx.x == 0) { oddNZ = 0; bigW = 0; }
    __syncthreads();
    for (int i = threadIdx.x; i < E; i += blockDim.x)
        if (eidx_w[2 * i + 1] != 0) atomicOr(&oddNZ, 1);
    for (int i = threadIdx.x; i < maskWords; i += blockDim.x)
        if (mask_w[i] > 1u) atomicOr(&bigW, 1);
    __syncthreads();
    if (threadIdx.x == 0) {
        g_eidx_is_i64 = (oddNZ == 0) ? 1 : 0;
        g_mask_is_u8  = bigW;
    }
}

// ---------------------------------------------------------------------------
// Kernel 0: per-cluster voxelization. grid (C, 4): pass split across y.
// ---------------------------------------------------------------------------
__global__ __launch_bounds__(256) void vox_kernel(
    const float* __restrict__ data,
    const int* __restrict__ clusts,
    const void* __restrict__ cmask)
{
    const int c = blockIdx.x;
    const int pass = blockIdx.y;
    const int t = threadIdx.x;

    __shared__ __align__(16) float ovy[NPT * VS];
    __shared__ __align__(16) float ovz[NPT * VS];
    __shared__ __align__(16) float sw[NPT];
    __shared__ __align__(16) float svx[NPT];
    __shared__ __align__(16) float spx[NPT], spy[NPT], spz[NPT];
    __shared__ __align__(16) float red[6 * NPT];

    const int mask_u8 = g_mask_is_u8;

    if (t < NPT) {
        int idx = clusts[c * NPT + t];
        int m;
        if (mask_u8) m = ((const unsigned char*)cmask)[c * NPT + t];
        else         m = ((const int*)cmask)[c * NPT + t];
        float x = data[idx * 5 + 0];
        float y = data[idx * 5 + 1];
        float z = data[idx * 5 + 2];
        float v = data[idx * 5 + 4];
        spx[t] = x; spy[t] = y; spz[t] = z;
        sw[t]  = m ? v : 0.0f;
        red[0*NPT + t] = m ? x :  1e9f;
        red[1*NPT + t] = m ? y :  1e9f;
        red[2*NPT + t] = m ? z :  1e9f;
        red[3*NPT + t] = m ? x : -1e9f;
        red[4*NPT + t] = m ? y : -1e9f;
        red[5*NPT + t] = m ? z : -1e9f;
    }
    __syncthreads();
    for (int s = 64; s > 0; s >>= 1) {
        if (t < s) {
            red[0*NPT + t] = fminf(red[0*NPT + t], red[0*NPT + t + s]);
            red[1*NPT + t] = fminf(red[1*NPT + t], red[1*NPT + t + s]);
            red[2*NPT + t] = fminf(red[2*NPT + t], red[2*NPT + t + s]);
            red[3*NPT + t] = fmaxf(red[3*NPT + t], red[3*NPT + t + s]);
            red[4*NPT + t] = fmaxf(red[4*NPT + t], red[4*NPT + t + s]);
            red[5*NPT + t] = fmaxf(red[5*NPT + t], red[5*NPT + t + s]);
        }
        __syncthreads();
    }
    const float minx = red[0], miny = red[NPT], minz = red[2*NPT];
    const float rx = red[3*NPT] - minx;
    const float ry = red[4*NPT] - miny;
    const float rz = red[5*NPT] - minz;
    const float mr = fmaxf(rx, fmaxf(ry, rz)) + 1.0f;
    const float gs  = 1.0f / mr;
    const float rgs = mr;
    const float ns  = 1.0f / (float)VS;

    {
        int p    = t & (NPT - 1);
        int half = t >> 7;
        float vy = (spy[p] - miny - ry * 0.5f - 0.5f) * gs + 0.5f;
        float vz = (spz[p] - minz - rz * 0.5f - 0.5f) * gs + 0.5f;
        for (int b = half * 16; b < half * 16 + 16; ++b) {
            float lo = (float)b * ns;
            float oy = fminf(vy + gs, lo + ns) - fmaxf(vy, lo);
            float oz = fminf(vz + gs, lo + ns) - fmaxf(vz, lo);
            ovy[p * VS + b] = fmaxf(oy, 0.0f) * rgs;
            ovz[p * VS + b] = fmaxf(oz, 0.0f) * rgs;
        }
        if (t < NPT)
            svx[t] = (spx[t] - minx - rx * 0.5f - 0.5f) * gs + 0.5f;
    }
    __syncthreads();

    float* outp = g_cvox + (size_t)c * VOXN;
    {
        int jk = t + pass * 256;
        int j = jk >> 5, k = jk & 31;
        float acc[VS];
#pragma unroll
        for (int i = 0; i < VS; ++i) acc[i] = 0.0f;
        for (int p = 0; p < NPT; ++p) {
            float ty = sw[p] * ovy[p * VS + j];
            if (ty != 0.0f) {
                float tz = ty * ovz[p * VS + k];
                float vx = svx[p];
#pragma unroll
                for (int i = 0; i < VS; ++i) {
                    float lo = (float)i * ns;
                    float ox = fminf(vx + gs, lo + ns) - fmaxf(vx, lo);
                    ox = fmaxf(ox, 0.0f) * rgs;
                    acc[i] += ox * tz;
                }
            }
        }
#pragma unroll
        for (int i = 0; i < VS; ++i)
            outp[i * (VS * VS) + jk] = acc[i];
    }
}

// ---------------------------------------------------------------------------
// Kernel 1: per-CLUSTER linear conv1 (1->16ch, 3^3, stride2). No bias/relu.
// ---------------------------------------------------------------------------
#define SD1 20
#define SD2 340           // 20*17
#define SIN_SZ (17*SD2)   // 5780

__global__ __launch_bounds__(256, 2) void conv1c_kernel(
    const float* __restrict__ W1)
{
    __shared__ __align__(16) float s_in[SIN_SZ];
    __shared__ __align__(16) float s_w[27 * 16];   // [tap][oc]

    const int blk  = blockIdx.x;
    const int c    = blk >> 3;
    const int tile = blk & 7;
    const int tz = (tile >> 2) & 1, tyy = (tile >> 1) & 1, tx = tile & 1;
    const int t = threadIdx.x;

    const float* __restrict__ A = g_cvox + (size_t)c * VOXN;
    const int z0 = tz * 16, y0 = tyy * 16, x0 = tx * 16;

    for (int i = t; i < SIN_SZ; i += 256) s_in[i] = 0.0f;
    for (int i = t; i < 432; i += 256) {
        int oc = i / 27, tap = i % 27;
        s_w[tap * 16 + oc] = W1[i];
    }
    __syncthreads();

    for (int i = t; i < 17 * 17 * 17; i += 256) {
        int z = i / 289, r = i % 289, y = r / 17, x = r % 17;
        int gz = z0 + z, gy = y0 + y, gx = x0 + x;
        if (gz < 32 && gy < 32 && gx < 32)
            s_in[z * SD2 + y * SD1 + x] = A[(gz * 32 + gy) * 32 + gx];
    }
    __syncthreads();

    const int sg = t & 63;
    const int lx = sg & 7, ly = sg >> 3;
    const int zq = t >> 6;
    const int laneoff = ly * 2 * SD1 + lx * 2;

    ull acc[2][8];
#pragma unroll
    for (int h = 0; h < 2; ++h)
#pragma unroll
        for (int m = 0; m < 8; ++m) acc[h][m] = 0ULL;

#pragma unroll
    for (int dz = 0; dz < 3; ++dz)
#pragma unroll
        for (int dy = 0; dy < 3; ++dy)
#pragma unroll
            for (int dx = 0; dx < 3; ++dx) {
                const int tap = (dz * 3 + dy) * 3 + dx;
                const ulonglong2 w01 = *(const ulonglong2*)&s_w[tap * 16];
                const ulonglong2 w23 = *(const ulonglong2*)&s_w[tap * 16 + 4];
                const ulonglong2 w45 = *(const ulonglong2*)&s_w[tap * 16 + 8];
                const ulonglong2 w67 = *(const ulonglong2*)&s_w[tap * 16 + 12];
                const int off = laneoff + dz * SD2 + dy * SD1 + dx;
#pragma unroll
                for (int h = 0; h < 2; ++h) {
                    float v = s_in[off + (zq * 2 + h) * 2 * SD2];
                    ull v2 = pk2(v, v);
                    fma2(acc[h][0], v2, w01.x);
                    fma2(acc[h][1], v2, w01.y);
                    fma2(acc[h][2], v2, w23.x);
                    fma2(acc[h][3], v2, w23.y);
                    fma2(acc[h][4], v2, w45.x);
                    fma2(acc[h][5], v2, w45.y);
                    fma2(acc[h][6], v2, w67.x);
                    fma2(acc[h][7], v2, w67.y);
                }
            }

    float* outp = g_c1c + (size_t)c * 16 * 4096;
#pragma unroll
    for (int h = 0; h < 2; ++h) {
        const int oz = tz * 8 + zq * 2 + h;
        const int oy = tyy * 8 + ly, ox = tx * 8 + lx;
        const int sp = oz * 256 + oy * 16 + ox;
#pragma unroll
        for (int m = 0; m < 8; ++m) {
            float2 p = upk2(acc[h][m]);
            outp[(2 * m)     * 4096 + sp] = p.x;
            outp[(2 * m + 1) * 4096 + sp] = p.y;
        }
    }
}

// ---------------------------------------------------------------------------
// Kernel 2: conv2 (16->32ch). grid=E, 256 thr (64 xy * 2 zh * 2 og).
// Thread = 16 oc (8 packed) x 4 z. float2+scalar input loads.
// ---------------------------------------------------------------------------
__global__ __launch_bounds__(256, 2) void conv2_kernel(
    const int* __restrict__ eidx,
    const float* __restrict__ W2,
    const float* __restrict__ b2,
    const float* __restrict__ b1,
    int E, int C)
{
    __shared__ __align__(16) float s_in[SIN_SZ];   // 23.1 KB
    __shared__ __align__(16) float s_w[27 * 32];   // [tap][oc]
    __shared__ __align__(16) float s_b[32];
    __shared__ __align__(16) float s_b1[16];

    const int e = blockIdx.x;
    const int t = threadIdx.x;

    int ca, cb;
    if (g_eidx_is_i64) { ca = eidx[2 * e]; cb = eidx[2 * (E + e)]; }
    else               { ca = eidx[e];     cb = eidx[E + e];       }
    ca = min(max(ca, 0), C - 1);
    cb = min(max(cb, 0), C - 1);

    for (int i = t; i < SIN_SZ; i += 256) s_in[i] = 0.0f;   // pads written once
    if (t < 32) s_b[t]  = b2[t];
    if (t < 16) s_b1[t] = b1[t];

    const int lx = t & 7, ly = (t >> 3) & 7;
    const int zh = (t >> 6) & 1;
    const int og = t >> 7;        // 0..1 -> 16 oc each, uniform per warp
    const int xyoff = ly * 2 * SD1 + lx * 2;

    ull acc[8][4];
#pragma unroll
    for (int m = 0; m < 8; ++m)
#pragma unroll
        for (int q = 0; q < 4; ++q) acc[m][q] = 0ULL;

    for (int ic = 0; ic < 16; ++ic) {
        __syncthreads();
        const float4* __restrict__ A4 =
            (const float4*)(g_c1c + ((size_t)ca * 16 + ic) * 4096);
        const float4* __restrict__ B4 =
            (const float4*)(g_c1c + ((size_t)cb * 16 + ic) * 4096);
        const float bias = s_b1[ic];
        for (int i4 = t; i4 < 1024; i4 += 256) {
            int z = i4 >> 6, rem = i4 & 63;
            int y = rem >> 2, x4 = rem & 3;
            float4 a = A4[i4];
            float4 b = B4[i4];
            float4 v;
            v.x = fmaxf(a.x + b.x + bias, 0.0f);
            v.y = fmaxf(a.y + b.y + bias, 0.0f);
            v.z = fmaxf(a.z + b.z + bias, 0.0f);
            v.w = fmaxf(a.w + b.w + bias, 0.0f);
            *(float4*)&s_in[z * SD2 + y * SD1 + x4 * 4] = v;
        }
        for (int i = t; i < 27 * 32; i += 256) {
            int tap = i >> 5, oc = i & 31;
            s_w[i] = W2[(oc * 16 + ic) * 27 + tap];
        }
        __syncthreads();
#pragma unroll
        for (int dz = 0; dz < 3; ++dz)
#pragma unroll
            for (int dy = 0; dy < 3; ++dy) {
                float2 v01[4];
                float  v2s[4];
#pragma unroll
                for (int q = 0; q < 4; ++q) {
                    const int off = (8 * zh + 2 * q + dz) * SD2
                                  + (2 * ly + dy) * SD1 + 2 * lx + xyoff - xyoff; // keep simple
                    const int o = (8 * zh + 2 * q + dz) * SD2 + (2 * ly + dy) * SD1 + 2 * lx;
                    v01[q] = *(const float2*)&s_in[o];
                    v2s[q] = s_in[o + 2];
                    (void)off;
                }
#pragma unroll
                for (int dx = 0; dx < 3; ++dx) {
                    const int tap = (dz * 3 + dy) * 3 + dx;
                    const ulonglong2 w0 = *(const ulonglong2*)&s_w[tap * 32 + og * 16];
                    const ulonglong2 w1 = *(const ulonglong2*)&s_w[tap * 32 + og * 16 + 4];
                    const ulonglong2 w2 = *(const ulonglong2*)&s_w[tap * 32 + og * 16 + 8];
                    const ulonglong2 w3 = *(const ulonglong2*)&s_w[tap * 32 + og * 16 + 12];
#pragma unroll
                    for (int q = 0; q < 4; ++q) {
                        float v = (dx == 0) ? v01[q].x : (dx == 1) ? v01[q].y : v2s[q];
                        ull vv = pk2(v, v);
                        fma2(acc[0][q], vv, w0.x);
                        fma2(acc[1][q], vv, w0.y);
                        fma2(acc[2][q], vv, w1.x);
                        fma2(acc[3][q], vv, w1.y);
                        fma2(acc[4][q], vv, w2.x);
                        fma2(acc[5][q], vv, w2.y);
                        fma2(acc[6][q], vv, w3.x);
                        fma2(acc[7][q], vv, w3.y);
                    }
                }
            }
    }

    float* outp = g_c2 + (size_t)e * 32 * 512;
#pragma unroll
    for (int m = 0; m < 8; ++m) {
        const int oc0 = og * 16 + 2 * m;
        const float b0 = s_b[oc0], b1v = s_b[oc0 + 1];
#pragma unroll
        for (int q = 0; q < 4; ++q) {
            float2 p = upk2(acc[m][q]);
            const int sidx = (4 * zh + q) * 64 + ly * 8 + lx;
            outp[oc0 * 512 + sidx]       = fmaxf(p.x + b0,  0.0f);
            outp[(oc0 + 1) * 512 + sidx] = fmaxf(p.y + b1v, 0.0f);
        }
    }
}

// ---------------------------------------------------------------------------
// Kernel 3: conv3 (32->64ch) + relu + mean-pool + FC. grid=E, 256 thr.
// Thread = 16 oc (8 packed) x 1 spatial.
// ---------------------------------------------------------------------------
#define C3S1 12
#define C3S2 108
#define C3SZ (9*C3S2)      // 972

__global__ __launch_bounds__(256, 4) void conv3_kernel(
    const float* __restrict__ W3,
    const float* __restrict__ b3,
    const float* __restrict__ Wfc,
    const float* __restrict__ bfc,
    float* __restrict__ out)
{
    __shared__ __align__(16) float s_in[C3SZ];
    __shared__ __align__(16) float s_w[27 * 64];   // [tap][oc]
    __shared__ __align__(16) float s_pool[64 * 65];
    __shared__ __align__(16) float s_pooled[64];

    const int e = blockIdx.x;
    const int t = threadIdx.x;
    const int og = t >> 6;     // 0..3 -> 16 oc each, uniform per warp
    const int s  = t & 63;
    const int lx = s & 3, ly = (s >> 2) & 3, lz = s >> 4;

    for (int i = t; i < C3SZ; i += 256) s_in[i] = 0.0f;

    ull acc[8];
#pragma unroll
    for (int m = 0; m < 8; ++m) acc[m] = 0ULL;

    for (int ic = 0; ic < 32; ++ic) {
        __syncthreads();
        const float4* __restrict__ src4 =
            (const float4*)(g_c2 + ((size_t)e * 32 + ic) * 512);
        if (t < 128) {
            float4 v = src4[t];
            int i = t * 4;
            int x = i & 7, y = (i >> 3) & 7, z = i >> 6;
            *(float4*)&s_in[z * C3S2 + y * C3S1 + x] = v;
        }
        for (int i = t; i < 27 * 64; i += 256) {
            int tap = i >> 6, oc = i & 63;
            s_w[i] = W3[(oc * 32 + ic) * 27 + tap];
        }
        __syncthreads();
#pragma unroll
        for (int dz = 0; dz < 3; ++dz)
#pragma unroll
            for (int dy = 0; dy < 3; ++dy) {
                const int o = (2 * lz + dz) * C3S2 + (2 * ly + dy) * C3S1 + 2 * lx;
                const float2 v01 = *(const float2*)&s_in[o];
                const float  v2s = s_in[o + 2];
#pragma unroll
                for (int dx = 0; dx < 3; ++dx) {
                    const int tap = (dz * 3 + dy) * 3 + dx;
                    const ulonglong2 w0 = *(const ulonglong2*)&s_w[tap * 64 + og * 16];
                    const ulonglong2 w1 = *(const ulonglong2*)&s_w[tap * 64 + og * 16 + 4];
                    const ulonglong2 w2 = *(const ulonglong2*)&s_w[tap * 64 + og * 16 + 8];
                    const ulonglong2 w3 = *(const ulonglong2*)&s_w[tap * 64 + og * 16 + 12];
                    float v = (dx == 0) ? v01.x : (dx == 1) ? v01.y : v2s;
                    ull vv = pk2(v, v);
                    fma2(acc[0], vv, w0.x);
                    fma2(acc[1], vv, w0.y);
                    fma2(acc[2], vv, w1.x);
                    fma2(acc[3], vv, w1.y);
                    fma2(acc[4], vv, w2.x);
                    fma2(acc[5], vv, w2.y);
                    fma2(acc[6], vv, w3.x);
                    fma2(acc[7], vv, w3.y);
                }
            }
    }
    __syncthreads();
#pragma unroll
    for (int m = 0; m < 8; ++m) {
        float2 p = upk2(acc[m]);
        const int oc0 = og * 16 + 2 * m;
        s_pool[s * 65 + oc0]     = fmaxf(p.x + __ldg(&b3[oc0]),     0.0f);
        s_pool[s * 65 + oc0 + 1] = fmaxf(p.y + __ldg(&b3[oc0 + 1]), 0.0f);
    }
    __syncthreads();
    if (t < 64) {
        float sum = 0.0f;
#pragma unroll 8
        for (int sp = 0; sp < 64; ++sp) sum += s_pool[sp * 65 + t];
        s_pooled[t] = sum * (1.0f / 64.0f);
    }
    __syncthreads();
    if (t < 64) {
        float r = bfc[t];
#pragma unroll 8
        for (int ic = 0; ic < 64; ++ic)
            r += s_pooled[ic] * __ldg(&Wfc[ic * 64 + t]);
        out[e * 64 + t] = r;
    }
}

// ---------------------------------------------------------------------------
extern "C" void kernel_launch(void* const* d_in, const int* in_sizes, int n_in,
                              void* d_out, int out_size)
{
    const float* data   = (const float*)d_in[0];
    const int*   clusts = (const int*)d_in[1];
    const void*  cmask  = d_in[2];
    const int*   eidx   = (const int*)d_in[3];
    const float* W1     = (const float*)d_in[4];
    const float* b1     = (const float*)d_in[5];
    const float* W2     = (const float*)d_in[6];
    const float* b2     = (const float*)d_in[7];
    const float* W3     = (const float*)d_in[8];
    const float* b3     = (const float*)d_in[9];
    const float* Wfc    = (const float*)d_in[10];
    const float* bfc    = (const float*)d_in[11];
    float*       out    = (float*)d_out;

    const int C = in_sizes[1] / NPT;   // 256
    const int E = in_sizes[3] / 2;     // 1024
    const int maskWords = in_sizes[2] / 4;

    detect_kernel<<<1, 256>>>(eidx, (const unsigned int*)cmask, E, maskWords);
    vox_kernel<<<dim3(C, 4), 256>>>(data, clusts, cmask);
    conv1c_kernel<<<C * 8, 256>>>(W1);
    conv2_kernel<<<E, 256>>>(eidx, W2, b2, b1, E, C);
    conv3_kernel<<<E, 256>>>(W3, b3, Wfc, bfc, out);
}

// round 7
// speedup vs baseline: 1.3710x; 1.3710x over previous
#include <cuda_runtime.h>
#include <cuda_bf16.h>

#define NCLUST 256
#define NPT    128
#define NEDGE  1024
#define VS     32
#define VOXN   (VS*VS*VS)   // 32768

typedef unsigned long long ull;

__device__ __forceinline__ ull pk2(float lo, float hi) {
    ull r; asm("mov.b64 %0, {%1,%2};" : "=l"(r) : "f"(lo), "f"(hi)); return r;
}
__device__ __forceinline__ void fma2(ull& d, ull a, ull b) {
    asm("fma.rn.f32x2 %0, %1, %2, %0;" : "+l"(d) : "l"(a), "l"(b));
}
__device__ __forceinline__ float2 upk2(ull v) {
    float2 r; asm("mov.b64 {%0,%1}, %2;" : "=f"(r.x), "=f"(r.y) : "l"(v)); return r;
}

// Scratch (device globals)
__device__ float g_cvox[NCLUST * VOXN];              // 32 MB
__device__ float g_c1c[NCLUST * 16 * 4096];          // 67 MB
__device__ float g_c2[NEDGE * 32 * 8 * 8 * 8];       // 67 MB
__device__ float g_w2t[16 * 27 * 32];                // W2 -> [ic][tap][oc]
__device__ float g_w3t[32 * 27 * 64];                // W3 -> [ic][tap][oc]
__device__ int   g_eidx_is_i64;
__device__ int   g_mask_is_u8;

// ---------------------------------------------------------------------------
// Kernel D: dtype layout detection
// ---------------------------------------------------------------------------
__global__ void detect_kernel(const int* __restrict__ eidx_w,
                              const unsigned int* __restrict__ mask_w,
                              int E, int maskWords)
{
    __shared__ int oddNZ, bigW;
    if (threadIdx.x == 0) { oddNZ = 0; bigW = 0; }
    __syncthreads();
    for (int i = threadIdx.x; i < E; i += blockDim.x)
        if (eidx_w[2 * i + 1] != 0) atomicOr(&oddNZ, 1);
    for (int i = threadIdx.x; i < maskWords; i += blockDim.x)
        if (mask_w[i] > 1u) atomicOr(&bigW, 1);
    __syncthreads();
    if (threadIdx.x == 0) {
        g_eidx_is_i64 = (oddNZ == 0) ? 1 : 0;
        g_mask_is_u8  = bigW;
    }
}

// ---------------------------------------------------------------------------
// Kernel W: transpose W2, W3 -> [ic][tap][oc] (one-time, tiny)
// ---------------------------------------------------------------------------
__global__ void wtrans_kernel(const float* __restrict__ W2,
                              const float* __restrict__ W3)
{
    int i = blockIdx.x * blockDim.x + threadIdx.x;
    if (i < 32 * 16 * 27) {
        int oc = i / (16 * 27), r = i % (16 * 27), ic = r / 27, tap = r % 27;
        g_w2t[(ic * 27 + tap) * 32 + oc] = W2[i];
    }
    if (i < 64 * 32 * 27) {
        int oc = i / (32 * 27), r = i % (32 * 27), ic = r / 27, tap = r % 27;
        g_w3t[(ic * 27 + tap) * 64 + oc] = W3[i];
    }
}

// ---------------------------------------------------------------------------
// Kernel 0: per-cluster voxelization (R5 form: grid C, 4 passes per block)
// ---------------------------------------------------------------------------
__global__ __launch_bounds__(256) void vox_kernel(
    const float* __restrict__ data,
    const int* __restrict__ clusts,
    const void* __restrict__ cmask)
{
    const int c = blockIdx.x;
    const int t = threadIdx.x;

    __shared__ __align__(16) float ovy[NPT * VS];
    __shared__ __align__(16) float ovz[NPT * VS];
    __shared__ __align__(16) float sw[NPT];
    __shared__ __align__(16) float svx[NPT];
    __shared__ __align__(16) float spx[NPT], spy[NPT], spz[NPT];
    __shared__ __align__(16) float red[6 * NPT];

    const int mask_u8 = g_mask_is_u8;

    if (t < NPT) {
        int idx = clusts[c * NPT + t];
        int m;
        if (mask_u8) m = ((const unsigned char*)cmask)[c * NPT + t];
        else         m = ((const int*)cmask)[c * NPT + t];
        float x = data[idx * 5 + 0];
        float y = data[idx * 5 + 1];
        float z = data[idx * 5 + 2];
        float v = data[idx * 5 + 4];
        spx[t] = x; spy[t] = y; spz[t] = z;
        sw[t]  = m ? v : 0.0f;
        red[0*NPT + t] = m ? x :  1e9f;
        red[1*NPT + t] = m ? y :  1e9f;
        red[2*NPT + t] = m ? z :  1e9f;
        red[3*NPT + t] = m ? x : -1e9f;
        red[4*NPT + t] = m ? y : -1e9f;
        red[5*NPT + t] = m ? z : -1e9f;
    }
    __syncthreads();
    for (int s = 64; s > 0; s >>= 1) {
        if (t < s) {
            red[0*NPT + t] = fminf(red[0*NPT + t], red[0*NPT + t + s]);
            red[1*NPT + t] = fminf(red[1*NPT + t], red[1*NPT + t + s]);
            red[2*NPT + t] = fminf(red[2*NPT + t], red[2*NPT + t + s]);
            red[3*NPT + t] = fmaxf(red[3*NPT + t], red[3*NPT + t + s]);
            red[4*NPT + t] = fmaxf(red[4*NPT + t], red[4*NPT + t + s]);
            red[5*NPT + t] = fmaxf(red[5*NPT + t], red[5*NPT + t + s]);
        }
        __syncthreads();
    }
    const float minx = red[0], miny = red[NPT], minz = red[2*NPT];
    const float rx = red[3*NPT] - minx;
    const float ry = red[4*NPT] - miny;
    const float rz = red[5*NPT] - minz;
    const float mr = fmaxf(rx, fmaxf(ry, rz)) + 1.0f;
    const float gs  = 1.0f / mr;
    const float rgs = mr;
    const float ns  = 1.0f / (float)VS;

    {
        int p    = t & (NPT - 1);
        int half = t >> 7;
        float vy = (spy[p] - miny - ry * 0.5f - 0.5f) * gs + 0.5f;
        float vz = (spz[p] - minz - rz * 0.5f - 0.5f) * gs + 0.5f;
        for (int b = half * 16; b < half * 16 + 16; ++b) {
            float lo = (float)b * ns;
            float oy = fminf(vy + gs, lo + ns) - fmaxf(vy, lo);
            float oz = fminf(vz + gs, lo + ns) - fmaxf(vz, lo);
            ovy[p * VS + b] = fmaxf(oy, 0.0f) * rgs;
            ovz[p * VS + b] = fmaxf(oz, 0.0f) * rgs;
        }
        if (t < NPT)
            svx[t] = (spx[t] - minx - rx * 0.5f - 0.5f) * gs + 0.5f;
    }
    __syncthreads();

    float* outp = g_cvox + (size_t)c * VOXN;
    for (int pass = 0; pass < 4; ++pass) {
        int jk = t + pass * 256;
        int j = jk >> 5, k = jk & 31;
        float acc[VS];
#pragma unroll
        for (int i = 0; i < VS; ++i) acc[i] = 0.0f;
        for (int p = 0; p < NPT; ++p) {
            float ty = sw[p] * ovy[p * VS + j];
            if (ty != 0.0f) {
                float tz = ty * ovz[p * VS + k];
                float vx = svx[p];
#pragma unroll
                for (int i = 0; i < VS; ++i) {
                    float lo = (float)i * ns;
                    float ox = fminf(vx + gs, lo + ns) - fmaxf(vx, lo);
                    ox = fmaxf(ox, 0.0f) * rgs;
                    acc[i] += ox * tz;
                }
            }
        }
#pragma unroll
        for (int i = 0; i < VS; ++i)
            outp[i * (VS * VS) + jk] = acc[i];
    }
}

// ---------------------------------------------------------------------------
// Kernel 1: per-CLUSTER linear conv1 (1->16ch, 3^3, stride2)
// ---------------------------------------------------------------------------
#define SD1 20
#define SD2 340           // 20*17
#define SIN_SZ (17*SD2)   // 5780

__global__ __launch_bounds__(256, 2) void conv1c_kernel(
    const float* __restrict__ W1)
{
    __shared__ __align__(16) float s_in[SIN_SZ];
    __shared__ __align__(16) float s_w[27 * 16];

    const int blk  = blockIdx.x;
    const int c    = blk >> 3;
    const int tile = blk & 7;
    const int tz = (tile >> 2) & 1, tyy = (tile >> 1) & 1, tx = tile & 1;
    const int t = threadIdx.x;

    const float* __restrict__ A = g_cvox + (size_t)c * VOXN;
    const int z0 = tz * 16, y0 = tyy * 16, x0 = tx * 16;

    for (int i = t; i < SIN_SZ; i += 256) s_in[i] = 0.0f;
    for (int i = t; i < 432; i += 256) {
        int oc = i / 27, tap = i % 27;
        s_w[tap * 16 + oc] = W1[i];
    }
    __syncthreads();

    for (int i = t; i < 17 * 17 * 17; i += 256) {
        int z = i / 289, r = i % 289, y = r / 17, x = r % 17;
        int gz = z0 + z, gy = y0 + y, gx = x0 + x;
        if (gz < 32 && gy < 32 && gx < 32)
            s_in[z * SD2 + y * SD1 + x] = A[(gz * 32 + gy) * 32 + gx];
    }
    __syncthreads();

    const int sg = t & 63;
    const int lx = sg & 7, ly = sg >> 3;
    const int zq = t >> 6;
    const int laneoff = ly * 2 * SD1 + lx * 2;

    ull acc[2][8];
#pragma unroll
    for (int h = 0; h < 2; ++h)
#pragma unroll
        for (int m = 0; m < 8; ++m) acc[h][m] = 0ULL;

#pragma unroll
    for (int dz = 0; dz < 3; ++dz)
#pragma unroll
        for (int dy = 0; dy < 3; ++dy)
#pragma unroll
            for (int dx = 0; dx < 3; ++dx) {
                const int tap = (dz * 3 + dy) * 3 + dx;
                const ulonglong2 w01 = *(const ulonglong2*)&s_w[tap * 16];
                const ulonglong2 w23 = *(const ulonglong2*)&s_w[tap * 16 + 4];
                const ulonglong2 w45 = *(const ulonglong2*)&s_w[tap * 16 + 8];
                const ulonglong2 w67 = *(const ulonglong2*)&s_w[tap * 16 + 12];
                const int off = laneoff + dz * SD2 + dy * SD1 + dx;
#pragma unroll
                for (int h = 0; h < 2; ++h) {
                    float v = s_in[off + (zq * 2 + h) * 2 * SD2];
                    ull v2 = pk2(v, v);
                    fma2(acc[h][0], v2, w01.x);
                    fma2(acc[h][1], v2, w01.y);
                    fma2(acc[h][2], v2, w23.x);
                    fma2(acc[h][3], v2, w23.y);
                    fma2(acc[h][4], v2, w45.x);
                    fma2(acc[h][5], v2, w45.y);
                    fma2(acc[h][6], v2, w67.x);
                    fma2(acc[h][7], v2, w67.y);
                }
            }

    float* outp = g_c1c + (size_t)c * 16 * 4096;
#pragma unroll
    for (int h = 0; h < 2; ++h) {
        const int oz = tz * 8 + zq * 2 + h;
        const int oy = tyy * 8 + ly, ox = tx * 8 + lx;
        const int sp = oz * 256 + oy * 16 + ox;
#pragma unroll
        for (int m = 0; m < 8; ++m) {
            float2 p = upk2(acc[h][m]);
            outp[(2 * m)     * 4096 + sp] = p.x;
            outp[(2 * m + 1) * 4096 + sp] = p.y;
        }
    }
}

// ---------------------------------------------------------------------------
// Kernel 2: conv2 (16->32ch). grid=E, 256 thr, double-staged over ic (2/stage).
// Thread = 16 oc (8 packed) x 4 z.
// ---------------------------------------------------------------------------
__global__ __launch_bounds__(256, 2) void conv2_kernel(
    const int* __restrict__ eidx,
    const float* __restrict__ b2,
    const float* __restrict__ b1,
    int E, int C)
{
    __shared__ __align__(16) float s_in[2][SIN_SZ];   // 46.2 KB
    __shared__ __align__(16) float s_w[2][27 * 32];   // 6.9 KB
    __shared__ __align__(16) float s_b[32];
    __shared__ __align__(16) float s_b1[16];

    const int e = blockIdx.x;
    const int t = threadIdx.x;

    int ca, cb;
    if (g_eidx_is_i64) { ca = eidx[2 * e]; cb = eidx[2 * (E + e)]; }
    else               { ca = eidx[e];     cb = eidx[E + e];       }
    ca = min(max(ca, 0), C - 1);
    cb = min(max(cb, 0), C - 1);

    for (int i = t; i < 2 * SIN_SZ; i += 256) ((float*)s_in)[i] = 0.0f;
    if (t < 32) s_b[t]  = b2[t];
    if (t < 16) s_b1[t] = b1[t];

    const int lx = t & 7, ly = (t >> 3) & 7;
    const int zh = (t >> 6) & 1;
    const int og = t >> 7;
    const int yrow = ly * 2 * SD1 + lx * 2;

    ull acc[8][4];
#pragma unroll
    for (int m = 0; m < 8; ++m)
#pragma unroll
        for (int q = 0; q < 4; ++q) acc[m][q] = 0ULL;

    const float4* __restrict__ A4 = (const float4*)(g_c1c + (size_t)ca * 16 * 4096);
    const float4* __restrict__ B4 = (const float4*)(g_c1c + (size_t)cb * 16 * 4096);

    for (int ics = 0; ics < 16; ics += 2) {
        __syncthreads();
        // fill 2 input planes (8 float4 per thread — batched LDGs)
#pragma unroll
        for (int r = 0; r < 8; ++r) {
            int i4 = t + r * 256;                 // 0..2047
            int buf = i4 >> 10, j = i4 & 1023;
            int z = j >> 6, rem = j & 63;
            int y = rem >> 2, x4 = rem & 3;
            const float bias = s_b1[ics + buf];
            float4 a = A4[(ics + buf) * 1024 + j];
            float4 b = B4[(ics + buf) * 1024 + j];
            float4 v;
            v.x = fmaxf(a.x + b.x + bias, 0.0f);
            v.y = fmaxf(a.y + b.y + bias, 0.0f);
            v.z = fmaxf(a.z + b.z + bias, 0.0f);
            v.w = fmaxf(a.w + b.w + bias, 0.0f);
            *(float4*)&s_in[buf][z * SD2 + y * SD1 + x4 * 4] = v;
        }
        // fill 2 ic of weights: contiguous [ic][tap][oc] — coalesced
        {
            const float4* wsrc = (const float4*)(g_w2t + ics * 864);
            float4* wdst = (float4*)s_w;
#pragma unroll
            for (int r = 0; r < 2; ++r) {
                int i4 = t + r * 256;
                if (i4 < 432) wdst[i4] = wsrc[i4];
            }
        }
        __syncthreads();
#pragma unroll
        for (int buf = 0; buf < 2; ++buf) {
            const float* sin = s_in[buf];
            const float* sw  = s_w[buf];
#pragma unroll
            for (int dz = 0; dz < 3; ++dz)
#pragma unroll
                for (int dy = 0; dy < 3; ++dy) {
                    float2 v01[4];
                    float  v2s[4];
#pragma unroll
                    for (int q = 0; q < 4; ++q) {
                        const int o = (8 * zh + 2 * q + dz) * SD2 + (2 * ly + dy) * SD1 + 2 * lx;
                        v01[q] = *(const float2*)&sin[o];
                        v2s[q] = sin[o + 2];
                    }
#pragma unroll
                    for (int dx = 0; dx < 3; ++dx) {
                        const int tap = (dz * 3 + dy) * 3 + dx;
                        const ulonglong2 w0 = *(const ulonglong2*)&sw[tap * 32 + og * 16];
                        const ulonglong2 w1 = *(const ulonglong2*)&sw[tap * 32 + og * 16 + 4];
                        const ulonglong2 w2 = *(const ulonglong2*)&sw[tap * 32 + og * 16 + 8];
                        const ulonglong2 w3 = *(const ulonglong2*)&sw[tap * 32 + og * 16 + 12];
#pragma unroll
                        for (int q = 0; q < 4; ++q) {
                            float v = (dx == 0) ? v01[q].x : (dx == 1) ? v01[q].y : v2s[q];
                            ull vv = pk2(v, v);
                            fma2(acc[0][q], vv, w0.x);
                            fma2(acc[1][q], vv, w0.y);
                            fma2(acc[2][q], vv, w1.x);
                            fma2(acc[3][q], vv, w1.y);
                            fma2(acc[4][q], vv, w2.x);
                            fma2(acc[5][q], vv, w2.y);
                            fma2(acc[6][q], vv, w3.x);
                            fma2(acc[7][q], vv, w3.y);
                        }
                    }
                }
        }
    }

    float* outp = g_c2 + (size_t)e * 32 * 512;
#pragma unroll
    for (int m = 0; m < 8; ++m) {
        const int oc0 = og * 16 + 2 * m;
        const float b0 = s_b[oc0], b1v = s_b[oc0 + 1];
#pragma unroll
        for (int q = 0; q < 4; ++q) {
            float2 p = upk2(acc[m][q]);
            const int sidx = (4 * zh + q) * 64 + ly * 8 + lx;
            outp[oc0 * 512 + sidx]       = fmaxf(p.x + b0,  0.0f);
            outp[(oc0 + 1) * 512 + sidx] = fmaxf(p.y + b1v, 0.0f);
        }
    }
}

// ---------------------------------------------------------------------------
// Kernel 3: conv3 (32->64ch) + relu + mean-pool + FC. grid=E, 256 thr.
// Double-staged over ic. Thread = 16 oc (8 packed) x 1 spatial.
// ---------------------------------------------------------------------------
#define C3S1 12
#define C3S2 108
#define C3SZ (9*C3S2)      // 972

__global__ __launch_bounds__(256, 3) void conv3_kernel(
    const float* __restrict__ b3,
    const float* __restrict__ Wfc,
    const float* __restrict__ bfc,
    float* __restrict__ out)
{
    __shared__ __align__(16) float s_in[2][C3SZ];      // 7.8 KB
    __shared__ __align__(16) float s_w[2][27 * 64];    // 13.8 KB
    __shared__ __align__(16) float s_pool[64 * 65];
    __shared__ __align__(16) float s_pooled[64];

    const int e = blockIdx.x;
    const int t = threadIdx.x;
    const int og = t >> 6;
    const int s  = t & 63;
    const int lx = s & 3, ly = (s >> 2) & 3, lz = s >> 4;

    for (int i = t; i < 2 * C3SZ; i += 256) ((float*)s_in)[i] = 0.0f;

    ull acc[8];
#pragma unroll
    for (int m = 0; m < 8; ++m) acc[m] = 0ULL;

    const float4* __restrict__ src4 = (const float4*)(g_c2 + (size_t)e * 32 * 512);

    for (int ics = 0; ics < 32; ics += 2) {
        __syncthreads();
        {   // input: 2 ic x 128 float4 = 256 -> one per thread
            int buf = t >> 7, j = t & 127;
            float4 v = src4[(ics + buf) * 128 + j];
            int i = j * 4;
            int x = i & 7, y = (i >> 3) & 7, z = i >> 6;
            *(float4*)&s_in[buf][z * C3S2 + y * C3S1 + x] = v;
        }
        {   // weights: 2 ic contiguous = 864 float4
            const float4* wsrc = (const float4*)(g_w3t + ics * 1728);
            float4* wdst = (float4*)s_w;
#pragma unroll
            for (int r = 0; r < 4; ++r) {
                int i4 = t + r * 256;
                if (i4 < 864) wdst[i4] = wsrc[i4];
            }
        }
        __syncthreads();
#pragma unroll
        for (int buf = 0; buf < 2; ++buf) {
            const float* sin = s_in[buf];
            const float* sw  = s_w[buf];
#pragma unroll
            for (int dz = 0; dz < 3; ++dz)
#pragma unroll
                for (int dy = 0; dy < 3; ++dy) {
                    const int o = (2 * lz + dz) * C3S2 + (2 * ly + dy) * C3S1 + 2 * lx;
                    const float2 v01 = *(const float2*)&sin[o];
                    const float  v2s = sin[o + 2];
#pragma unroll
                    for (int dx = 0; dx < 3; ++dx) {
                        const int tap = (dz * 3 + dy) * 3 + dx;
                        const ulonglong2 w0 = *(const ulonglong2*)&sw[tap * 64 + og * 16];
                        const ulonglong2 w1 = *(const ulonglong2*)&sw[tap * 64 + og * 16 + 4];
                        const ulonglong2 w2 = *(const ulonglong2*)&sw[tap * 64 + og * 16 + 8];
                        const ulonglong2 w3 = *(const ulonglong2*)&sw[tap * 64 + og * 16 + 12];
                        float v = (dx == 0) ? v01.x : (dx == 1) ? v01.y : v2s;
                        ull vv = pk2(v, v);
                        fma2(acc[0], vv, w0.x);
                        fma2(acc[1], vv, w0.y);
                        fma2(acc[2], vv, w1.x);
                        fma2(acc[3], vv, w1.y);
                        fma2(acc[4], vv, w2.x);
                        fma2(acc[5], vv, w2.y);
                        fma2(acc[6], vv, w3.x);
                        fma2(acc[7], vv, w3.y);
                    }
                }
        }
    }
    __syncthreads();
#pragma unroll
    for (int m = 0; m < 8; ++m) {
        float2 p = upk2(acc[m]);
        const int oc0 = og * 16 + 2 * m;
        s_pool[s * 65 + oc0]     = fmaxf(p.x + __ldg(&b3[oc0]),     0.0f);
        s_pool[s * 65 + oc0 + 1] = fmaxf(p.y + __ldg(&b3[oc0 + 1]), 0.0f);
    }
    __syncthreads();
    if (t < 64) {
        float sum = 0.0f;
#pragma unroll 8
        for (int sp = 0; sp < 64; ++sp) sum += s_pool[sp * 65 + t];
        s_pooled[t] = sum * (1.0f / 64.0f);
    }
    __syncthreads();
    if (t < 64) {
        float r = bfc[t];
#pragma unroll 8
        for (int ic = 0; ic < 64; ++ic)
            r += s_pooled[ic] * __ldg(&Wfc[ic * 64 + t]);
        out[e * 64 + t] = r;
    }
}

// ---------------------------------------------------------------------------
extern "C" void kernel_launch(void* const* d_in, const int* in_sizes, int n_in,
                              void* d_out, int out_size)
{
    const float* data   = (const float*)d_in[0];
    const int*   clusts = (const int*)d_in[1];
    const void*  cmask  = d_in[2];
    const int*   eidx   = (const int*)d_in[3];
    const float* W1     = (const float*)d_in[4];
    const float* b1     = (const float*)d_in[5];
    const float* W2     = (const float*)d_in[6];
    const float* b2     = (const float*)d_in[7];
    const float* W3     = (const float*)d_in[8];
    const float* b3     = (const float*)d_in[9];
    const float* Wfc    = (const float*)d_in[10];
    const float* bfc    = (const float*)d_in[11];
    float*       out    = (float*)d_out;

    const int C = in_sizes[1] / NPT;   // 256
    const int E = in_sizes[3] / 2;     // 1024
    const int maskWords = in_sizes[2] / 4;

    detect_kernel<<<1, 256>>>(eidx, (const unsigned int*)cmask, E, maskWords);
    wtrans_kernel<<<216, 256>>>(W2, W3);
    vox_kernel<<<C, 256>>>(data, clusts, cmask);
    conv1c_kernel<<<C * 8, 256>>>(W1);
    conv2_kernel<<<E, 256>>>(eidx, b2, b1, E, C);
    conv3_kernel<<<E, 256>>>(b3, Wfc, bfc, out);
}

// round 8
// speedup vs baseline: 1.5639x; 1.1407x over previous
#include <cuda_runtime.h>
#include <cuda_bf16.h>

#define NCLUST 256
#define NPT    128
#define NEDGE  1024
#define VS     32
#define VOXN   (VS*VS*VS)   // 32768

typedef unsigned long long ull;

__device__ __forceinline__ ull pk2(float lo, float hi) {
    ull r; asm("mov.b64 %0, {%1,%2};" : "=l"(r) : "f"(lo), "f"(hi)); return r;
}
__device__ __forceinline__ void fma2(ull& d, ull a, ull b) {
    asm("fma.rn.f32x2 %0, %1, %2, %0;" : "+l"(d) : "l"(a), "l"(b));
}
__device__ __forceinline__ float2 upk2(ull v) {
    float2 r; asm("mov.b64 {%0,%1}, %2;" : "=f"(r.x), "=f"(r.y) : "l"(v)); return r;
}

// Scratch (device globals)
__device__ float g_cvox[NCLUST * VOXN];              // 32 MB
__device__ float g_c1c[NCLUST * 16 * 4096];          // 67 MB
__device__ float g_c2[NEDGE * 32 * 8 * 8 * 8];       // 67 MB
__device__ float g_w2t[16 * 27 * 32];                // W2 -> [ic][tap][oc]
__device__ float g_w3t[32 * 27 * 64];                // W3 -> [ic][tap][oc]
__device__ int   g_eidx_is_i64;
__device__ int   g_mask_is_u8;

// ---------------------------------------------------------------------------
// Kernel D: dtype layout detection
// ---------------------------------------------------------------------------
__global__ void detect_kernel(const int* __restrict__ eidx_w,
                              const unsigned int* __restrict__ mask_w,
                              int E, int maskWords)
{
    __shared__ int oddNZ, bigW;
    if (threadIdx.x == 0) { oddNZ = 0; bigW = 0; }
    __syncthreads();
    for (int i = threadIdx.x; i < E; i += blockDim.x)
        if (eidx_w[2 * i + 1] != 0) atomicOr(&oddNZ, 1);
    for (int i = threadIdx.x; i < maskWords; i += blockDim.x)
        if (mask_w[i] > 1u) atomicOr(&bigW, 1);
    __syncthreads();
    if (threadIdx.x == 0) {
        g_eidx_is_i64 = (oddNZ == 0) ? 1 : 0;
        g_mask_is_u8  = bigW;
    }
}

// ---------------------------------------------------------------------------
// Kernel W: transpose W2, W3 -> [ic][tap][oc]
// ---------------------------------------------------------------------------
__global__ void wtrans_kernel(const float* __restrict__ W2,
                              const float* __restrict__ W3)
{
    int i = blockIdx.x * blockDim.x + threadIdx.x;
    if (i < 32 * 16 * 27) {
        int oc = i / (16 * 27), r = i % (16 * 27), ic = r / 27, tap = r % 27;
        g_w2t[(ic * 27 + tap) * 32 + oc] = W2[i];
    }
    if (i < 64 * 32 * 27) {
        int oc = i / (32 * 27), r = i % (32 * 27), ic = r / 27, tap = r % 27;
        g_w3t[(ic * 27 + tap) * 64 + oc] = W3[i];
    }
}

// ---------------------------------------------------------------------------
// Kernel 0: per-cluster voxelization. Dynamic smem: ovy/ovz/ovx tables.
// ---------------------------------------------------------------------------
#define VOX_SMEM ((3 * NPT * VS + 4 * NPT + 6 * NPT) * 4)   // 54272 B

__global__ __launch_bounds__(256) void vox_kernel(
    const float* __restrict__ data,
    const int* __restrict__ clusts,
    const void* __restrict__ cmask)
{
    extern __shared__ __align__(16) float dsm[];
    float* ovy = dsm;                       // NPT*VS
    float* ovz = dsm + NPT * VS;            // NPT*VS
    float* ovx = dsm + 2 * NPT * VS;        // NPT*VS
    float* sw  = dsm + 3 * NPT * VS;        // NPT
    float* spx = sw  + NPT;                 // NPT
    float* spy = spx + NPT;
    float* spz = spy + NPT;
    float* red = spz + NPT;                 // 6*NPT

    const int c = blockIdx.x;
    const int t = threadIdx.x;
    const int mask_u8 = g_mask_is_u8;

    if (t < NPT) {
        int idx = clusts[c * NPT + t];
        int m;
        if (mask_u8) m = ((const unsigned char*)cmask)[c * NPT + t];
        else         m = ((const int*)cmask)[c * NPT + t];
        float x = data[idx * 5 + 0];
        float y = data[idx * 5 + 1];
        float z = data[idx * 5 + 2];
        float v = data[idx * 5 + 4];
        spx[t] = x; spy[t] = y; spz[t] = z;
        sw[t]  = m ? v : 0.0f;
        red[0*NPT + t] = m ? x :  1e9f;
        red[1*NPT + t] = m ? y :  1e9f;
        red[2*NPT + t] = m ? z :  1e9f;
        red[3*NPT + t] = m ? x : -1e9f;
        red[4*NPT + t] = m ? y : -1e9f;
        red[5*NPT + t] = m ? z : -1e9f;
    }
    __syncthreads();
    for (int s = 64; s > 0; s >>= 1) {
        if (t < s) {
            red[0*NPT + t] = fminf(red[0*NPT + t], red[0*NPT + t + s]);
            red[1*NPT + t] = fminf(red[1*NPT + t], red[1*NPT + t + s]);
            red[2*NPT + t] = fminf(red[2*NPT + t], red[2*NPT + t + s]);
            red[3*NPT + t] = fmaxf(red[3*NPT + t], red[3*NPT + t + s]);
            red[4*NPT + t] = fmaxf(red[4*NPT + t], red[4*NPT + t + s]);
            red[5*NPT + t] = fmaxf(red[5*NPT + t], red[5*NPT + t + s]);
        }
        __syncthreads();
    }
    const float minx = red[0], miny = red[NPT], minz = red[2*NPT];
    const float rx = red[3*NPT] - minx;
    const float ry = red[4*NPT] - miny;
    const float rz = red[5*NPT] - minz;
    const float mr = fmaxf(rx, fmaxf(ry, rz)) + 1.0f;
    const float gs  = 1.0f / mr;
    const float rgs = mr;
    const float ns  = 1.0f / (float)VS;

    {
        int p    = t & (NPT - 1);
        int half = t >> 7;
        float vx = (spx[p] - minx - rx * 0.5f - 0.5f) * gs + 0.5f;
        float vy = (spy[p] - miny - ry * 0.5f - 0.5f) * gs + 0.5f;
        float vz = (spz[p] - minz - rz * 0.5f - 0.5f) * gs + 0.5f;
        for (int b = half * 16; b < half * 16 + 16; ++b) {
            float lo = (float)b * ns;
            float ox = fminf(vx + gs, lo + ns) - fmaxf(vx, lo);
            float oy = fminf(vy + gs, lo + ns) - fmaxf(vy, lo);
            float oz = fminf(vz + gs, lo + ns) - fmaxf(vz, lo);
            ovx[p * VS + b] = fmaxf(ox, 0.0f) * rgs;
            ovy[p * VS + b] = fmaxf(oy, 0.0f) * rgs;
            ovz[p * VS + b] = fmaxf(oz, 0.0f) * rgs;
        }
    }
    __syncthreads();

    float* outp = g_cvox + (size_t)c * VOXN;
    for (int pass = 0; pass < 4; ++pass) {
        int jk = t + pass * 256;
        int j = jk >> 5, k = jk & 31;
        float acc[VS];
#pragma unroll
        for (int i = 0; i < VS; ++i) acc[i] = 0.0f;
        for (int p = 0; p < NPT; ++p) {
            float ty = sw[p] * ovy[p * VS + j];
            if (ty != 0.0f) {
                float tz = ty * ovz[p * VS + k];
                const float4* ox4 = (const float4*)&ovx[p * VS];
#pragma unroll
                for (int i4 = 0; i4 < 8; ++i4) {
                    float4 o = ox4[i4];
                    acc[i4 * 4 + 0] += o.x * tz;
                    acc[i4 * 4 + 1] += o.y * tz;
                    acc[i4 * 4 + 2] += o.z * tz;
                    acc[i4 * 4 + 3] += o.w * tz;
                }
            }
        }
#pragma unroll
        for (int i = 0; i < VS; ++i)
            outp[i * (VS * VS) + jk] = acc[i];
    }
}

// ---------------------------------------------------------------------------
// Kernel 1: per-CLUSTER linear conv1, z-slab tiling. grid = C*4, 256 thr.
// Block: 9 full 32x32 input planes, coalesced fill. Thread = 16oc x 4z.
// ---------------------------------------------------------------------------
#define C1SD 36
#define C1PL (33 * C1SD)     // 1188
#define C1SZ (9 * C1PL)      // 10692 floats

__global__ __launch_bounds__(256, 2) void conv1c_kernel(
    const float* __restrict__ W1)
{
    __shared__ __align__(16) float s_in[C1SZ];   // 42.8 KB
    __shared__ __align__(16) float s_w[27 * 16];

    const int c    = blockIdx.x >> 2;
    const int slab = blockIdx.x & 3;
    const int t = threadIdx.x;
    const float* __restrict__ A = g_cvox + (size_t)c * VOXN;

    for (int i = t; i < C1SZ; i += 256) s_in[i] = 0.0f;
    for (int i = t; i < 432; i += 256) {
        int oc = i / 27, tap = i % 27;
        s_w[tap * 16 + oc] = W1[i];
    }
    __syncthreads();

    const int z0 = slab * 8;
#pragma unroll
    for (int r = 0; r < 9; ++r) {
        int i4 = t + r * 256;            // 0..2303
        int zz = i4 >> 8, j = i4 & 255;  // plane, 256 float4 per plane
        int gz = z0 + zz;
        if (gz < 32) {
            float4 v = *(const float4*)&A[gz * 1024 + j * 4];
            *(float4*)&s_in[zz * C1PL + (j >> 3) * C1SD + (j & 7) * 4] = v;
        }
    }
    __syncthreads();

    const int x = t & 15, y = t >> 4;

    ull acc[4][8];
#pragma unroll
    for (int q = 0; q < 4; ++q)
#pragma unroll
        for (int m = 0; m < 8; ++m) acc[q][m] = 0ULL;

#pragma unroll
    for (int dz = 0; dz < 3; ++dz)
#pragma unroll
        for (int dy = 0; dy < 3; ++dy) {
            float2 v01[4];
            float  v2s[4];
#pragma unroll
            for (int q = 0; q < 4; ++q) {
                const int o = (2 * q + dz) * C1PL + (2 * y + dy) * C1SD + 2 * x;
                v01[q] = *(const float2*)&s_in[o];
                v2s[q] = s_in[o + 2];
            }
#pragma unroll
            for (int dx = 0; dx < 3; ++dx) {
                const int tap = (dz * 3 + dy) * 3 + dx;
                const ulonglong2 w01 = *(const ulonglong2*)&s_w[tap * 16];
                const ulonglong2 w23 = *(const ulonglong2*)&s_w[tap * 16 + 4];
                const ulonglong2 w45 = *(const ulonglong2*)&s_w[tap * 16 + 8];
                const ulonglong2 w67 = *(const ulonglong2*)&s_w[tap * 16 + 12];
#pragma unroll
                for (int q = 0; q < 4; ++q) {
                    float v = (dx == 0) ? v01[q].x : (dx == 1) ? v01[q].y : v2s[q];
                    ull vv = pk2(v, v);
                    fma2(acc[q][0], vv, w01.x);
                    fma2(acc[q][1], vv, w01.y);
                    fma2(acc[q][2], vv, w23.x);
                    fma2(acc[q][3], vv, w23.y);
                    fma2(acc[q][4], vv, w45.x);
                    fma2(acc[q][5], vv, w45.y);
                    fma2(acc[q][6], vv, w67.x);
                    fma2(acc[q][7], vv, w67.y);
                }
            }
        }

    float* outp = g_c1c + (size_t)c * 16 * 4096;
#pragma unroll
    for (int q = 0; q < 4; ++q) {
        const int oz = slab * 4 + q;
        const int sp = oz * 256 + y * 16 + x;
#pragma unroll
        for (int m = 0; m < 8; ++m) {
            float2 p = upk2(acc[q][m]);
            outp[(2 * m)     * 4096 + sp] = p.x;
            outp[(2 * m + 1) * 4096 + sp] = p.y;
        }
    }
}

// ---------------------------------------------------------------------------
// Kernel 2: conv2 (16->32ch). grid=E, 256 thr, 4-ic stages, dynamic smem.
// Thread = 16 oc (8 packed) x 4 z.
// ---------------------------------------------------------------------------
#define SD1 20
#define SD2 340           // 20*17
#define SIN_SZ (17*SD2)   // 5780
#define C2_SMEM ((4 * SIN_SZ + 4 * 864 + 48) * 4)   // 106688 B

__global__ __launch_bounds__(256, 2) void conv2_kernel(
    const int* __restrict__ eidx,
    const float* __restrict__ b2,
    const float* __restrict__ b1,
    int E, int C)
{
    extern __shared__ __align__(16) float c2sm[];
    float* s_in0 = c2sm;                      // 4 * SIN_SZ
    float* s_wb  = c2sm + 4 * SIN_SZ;         // 4 * 864
    float* s_b   = s_wb + 4 * 864;            // 32
    float* s_b1  = s_b + 32;                  // 16

    const int e = blockIdx.x;
    const int t = threadIdx.x;

    int ca, cb;
    if (g_eidx_is_i64) { ca = eidx[2 * e]; cb = eidx[2 * (E + e)]; }
    else               { ca = eidx[e];     cb = eidx[E + e];       }
    ca = min(max(ca, 0), C - 1);
    cb = min(max(cb, 0), C - 1);

    for (int i = t; i < 4 * SIN_SZ; i += 256) s_in0[i] = 0.0f;
    if (t < 32) s_b[t]  = b2[t];
    if (t < 16) s_b1[t] = b1[t];

    const int lx = t & 7, ly = (t >> 3) & 7;
    const int zh = (t >> 6) & 1;
    const int og = t >> 7;

    ull acc[8][4];
#pragma unroll
    for (int m = 0; m < 8; ++m)
#pragma unroll
        for (int q = 0; q < 4; ++q) acc[m][q] = 0ULL;

    const float4* __restrict__ A4 = (const float4*)(g_c1c + (size_t)ca * 16 * 4096);
    const float4* __restrict__ B4 = (const float4*)(g_c1c + (size_t)cb * 16 * 4096);

    for (int ics = 0; ics < 16; ics += 4) {
        __syncthreads();
        // fill 4 input planes (16 float4 pairs per thread — batched LDGs)
#pragma unroll
        for (int r = 0; r < 16; ++r) {
            int i4 = t + r * 256;                 // 0..4095
            int buf = i4 >> 10, j = i4 & 1023;
            int z = j >> 6, rem = j & 63;
            int y = rem >> 2, x4 = rem & 3;
            const float bias = s_b1[ics + buf];
            float4 a = A4[(ics + buf) * 1024 + j];
            float4 b = B4[(ics + buf) * 1024 + j];
            float4 v;
            v.x = fmaxf(a.x + b.x + bias, 0.0f);
            v.y = fmaxf(a.y + b.y + bias, 0.0f);
            v.z = fmaxf(a.z + b.z + bias, 0.0f);
            v.w = fmaxf(a.w + b.w + bias, 0.0f);
            *(float4*)&s_in0[buf * SIN_SZ + z * SD2 + y * SD1 + x4 * 4] = v;
        }
        // weights: 4 ic contiguous = 864 float4
        {
            const float4* wsrc = (const float4*)(g_w2t + ics * 864);
            float4* wdst = (float4*)s_wb;
#pragma unroll
            for (int r = 0; r < 4; ++r) {
                int i4 = t + r * 256;
                if (i4 < 864) wdst[i4] = wsrc[i4];
            }
        }
        __syncthreads();
#pragma unroll
        for (int buf = 0; buf < 4; ++buf) {
            const float* sin = s_in0 + buf * SIN_SZ;
            const float* sw  = s_wb + buf * 864;
#pragma unroll
            for (int dz = 0; dz < 3; ++dz)
#pragma unroll
                for (int dy = 0; dy < 3; ++dy) {
                    float2 v01[4];
                    float  v2s[4];
#pragma unroll
                    for (int q = 0; q < 4; ++q) {
                        const int o = (8 * zh + 2 * q + dz) * SD2 + (2 * ly + dy) * SD1 + 2 * lx;
                        v01[q] = *(const float2*)&sin[o];
                        v2s[q] = sin[o + 2];
                    }
#pragma unroll
                    for (int dx = 0; dx < 3; ++dx) {
                        const int tap = (dz * 3 + dy) * 3 + dx;
                        const ulonglong2 w0 = *(const ulonglong2*)&sw[tap * 32 + og * 16];
                        const ulonglong2 w1 = *(const ulonglong2*)&sw[tap * 32 + og * 16 + 4];
                        const ulonglong2 w2 = *(const ulonglong2*)&sw[tap * 32 + og * 16 + 8];
                        const ulonglong2 w3 = *(const ulonglong2*)&sw[tap * 32 + og * 16 + 12];
#pragma unroll
                        for (int q = 0; q < 4; ++q) {
                            float v = (dx == 0) ? v01[q].x : (dx == 1) ? v01[q].y : v2s[q];
                            ull vv = pk2(v, v);
                            fma2(acc[0][q], vv, w0.x);
                            fma2(acc[1][q], vv, w0.y);
                            fma2(acc[2][q], vv, w1.x);
                            fma2(acc[3][q], vv, w1.y);
                            fma2(acc[4][q], vv, w2.x);
                            fma2(acc[5][q], vv, w2.y);
                            fma2(acc[6][q], vv, w3.x);
                            fma2(acc[7][q], vv, w3.y);
                        }
                    }
                }
        }
    }

    float* outp = g_c2 + (size_t)e * 32 * 512;
#pragma unroll
    for (int m = 0; m < 8; ++m) {
        const int oc0 = og * 16 + 2 * m;
        const float b0 = s_b[oc0], b1v = s_b[oc0 + 1];
#pragma unroll
        for (int q = 0; q < 4; ++q) {
            float2 p = upk2(acc[m][q]);
            const int sidx = (4 * zh + q) * 64 + ly * 8 + lx;
            outp[oc0 * 512 + sidx]       = fmaxf(p.x + b0,  0.0f);
            outp[(oc0 + 1) * 512 + sidx] = fmaxf(p.y + b1v, 0.0f);
        }
    }
}

// ---------------------------------------------------------------------------
// Kernel 3: conv3 (32->64ch) + relu + mean-pool + FC. grid=E, 256 thr.
// Double-staged over ic. Thread = 16 oc (8 packed) x 1 spatial.
// ---------------------------------------------------------------------------
#define C3S1 12
#define C3S2 108
#define C3SZ (9*C3S2)      // 972

__global__ __launch_bounds__(256, 3) void conv3_kernel(
    const float* __restrict__ b3,
    const float* __restrict__ Wfc,
    const float* __restrict__ bfc,
    float* __restrict__ out)
{
    __shared__ __align__(16) float s_in[2][C3SZ];
    __shared__ __align__(16) float s_w[2][27 * 64];
    __shared__ __align__(16) float s_pool[64 * 65];
    __shared__ __align__(16) float s_pooled[64];

    const int e = blockIdx.x;
    const int t = threadIdx.x;
    const int og = t >> 6;
    const int s  = t & 63;
    const int lx = s & 3, ly = (s >> 2) & 3, lz = s >> 4;

    for (int i = t; i < 2 * C3SZ; i += 256) ((float*)s_in)[i] = 0.0f;

    ull acc[8];
#pragma unroll
    for (int m = 0; m < 8; ++m) acc[m] = 0ULL;

    const float4* __restrict__ src4 = (const float4*)(g_c2 + (size_t)e * 32 * 512);

    for (int ics = 0; ics < 32; ics += 2) {
        __syncthreads();
        {
            int buf = t >> 7, j = t & 127;
            float4 v = src4[(ics + buf) * 128 + j];
            int i = j * 4;
            int x = i & 7, y = (i >> 3) & 7, z = i >> 6;
            *(float4*)&s_in[buf][z * C3S2 + y * C3S1 + x] = v;
        }
        {
            const float4* wsrc = (const float4*)(g_w3t + ics * 1728);
            float4* wdst = (float4*)s_w;
#pragma unroll
            for (int r = 0; r < 4; ++r) {
                int i4 = t + r * 256;
                if (i4 < 864) wdst[i4] = wsrc[i4];
            }
        }
        __syncthreads();
#pragma unroll
        for (int buf = 0; buf < 2; ++buf) {
            const float* sin = s_in[buf];
            const float* sw  = s_w[buf];
#pragma unroll
            for (int dz = 0; dz < 3; ++dz)
#pragma unroll
                for (int dy = 0; dy < 3; ++dy) {
                    const int o = (2 * lz + dz) * C3S2 + (2 * ly + dy) * C3S1 + 2 * lx;
                    const float2 v01 = *(const float2*)&sin[o];
                    const float  v2s = sin[o + 2];
#pragma unroll
                    for (int dx = 0; dx < 3; ++dx) {
                        const int tap = (dz * 3 + dy) * 3 + dx;
                        const ulonglong2 w0 = *(const ulonglong2*)&sw[tap * 64 + og * 16];
                        const ulonglong2 w1 = *(const ulonglong2*)&sw[tap * 64 + og * 16 + 4];
                        const ulonglong2 w2 = *(const ulonglong2*)&sw[tap * 64 + og * 16 + 8];
                        const ulonglong2 w3 = *(const ulonglong2*)&sw[tap * 64 + og * 16 + 12];
                        float v = (dx == 0) ? v01.x : (dx == 1) ? v01.y : v2s;
                        ull vv = pk2(v, v);
                        fma2(acc[0], vv, w0.x);
                        fma2(acc[1], vv, w0.y);
                        fma2(acc[2], vv, w1.x);
                        fma2(acc[3], vv, w1.y);
                        fma2(acc[4], vv, w2.x);
                        fma2(acc[5], vv, w2.y);
                        fma2(acc[6], vv, w3.x);
                        fma2(acc[7], vv, w3.y);
                    }
                }
        }
    }
    __syncthreads();
#pragma unroll
    for (int m = 0; m < 8; ++m) {
        float2 p = upk2(acc[m]);
        const int oc0 = og * 16 + 2 * m;
        s_pool[s * 65 + oc0]     = fmaxf(p.x + __ldg(&b3[oc0]),     0.0f);
        s_pool[s * 65 + oc0 + 1] = fmaxf(p.y + __ldg(&b3[oc0 + 1]), 0.0f);
    }
    __syncthreads();
    if (t < 64) {
        float sum = 0.0f;
#pragma unroll 8
        for (int sp = 0; sp < 64; ++sp) sum += s_pool[sp * 65 + t];
        s_pooled[t] = sum * (1.0f / 64.0f);
    }
    __syncthreads();
    if (t < 64) {
        float r = bfc[t];
#pragma unroll 8
        for (int ic = 0; ic < 64; ++ic)
            r += s_pooled[ic] * __ldg(&Wfc[ic * 64 + t]);
        out[e * 64 + t] = r;
    }
}

// ---------------------------------------------------------------------------
extern "C" void kernel_launch(void* const* d_in, const int* in_sizes, int n_in,
                              void* d_out, int out_size)
{
    const float* data   = (const float*)d_in[0];
    const int*   clusts = (const int*)d_in[1];
    const void*  cmask  = d_in[2];
    const int*   eidx   = (const int*)d_in[3];
    const float* W1     = (const float*)d_in[4];
    const float* b1     = (const float*)d_in[5];
    const float* W2     = (const float*)d_in[6];
    const float* b2     = (const float*)d_in[7];
    const float* W3     = (const float*)d_in[8];
    const float* b3     = (const float*)d_in[9];
    const float* Wfc    = (const float*)d_in[10];
    const float* bfc    = (const float*)d_in[11];
    float*       out    = (float*)d_out;

    const int C = in_sizes[1] / NPT;   // 256
    const int E = in_sizes[3] / 2;     // 1024
    const int maskWords = in_sizes[2] / 4;

    // opt-in dynamic smem (idempotent; immediate host-side API, not captured)
    cudaFuncSetAttribute(vox_kernel,
        cudaFuncAttributeMaxDynamicSharedMemorySize, VOX_SMEM);
    cudaFuncSetAttribute(conv2_kernel,
        cudaFuncAttributeMaxDynamicSharedMemorySize, C2_SMEM);

    detect_kernel<<<1, 256>>>(eidx, (const unsigned int*)cmask, E, maskWords);
    wtrans_kernel<<<216, 256>>>(W2, W3);
    vox_kernel<<<C, 256, VOX_SMEM>>>(data, clusts, cmask);
    conv1c_kernel<<<C * 4, 256>>>(W1);
    conv2_kernel<<<E, 256, C2_SMEM>>>(eidx, b2, b1, E, C);
    conv3_kernel<<<E, 256>>>(b3, Wfc, bfc, out);
}